// round 2
// baseline (speedup 1.0000x reference)
#include <cuda_runtime.h>

#define BQ 2
#define NPTS 512
#define INDIM 512
#define MEMD 300
#define HIDD 64
#define NEG 0.01f
#define NN (NPTS*NPTS)
#define ROWS (BQ*NPTS)   // 1024

// ---------------- scratch (device globals; no allocation) ----------------
__device__ float g_h[ROWS*MEMD];        // per-layer node projections
__device__ float g_s[ROWS*2*HIDD];      // [s_i(+a1_b) | s_j] per row
__device__ float g_u[BQ*NN];            // logits, then exp weights
__device__ float g_f[ROWS*MEMD];        // layer-0 output
__device__ float g_sum[BQ];
__device__ unsigned g_maxord[BQ];

__device__ __forceinline__ unsigned f2ord(float f) {
    unsigned u = __float_as_uint(f);
    return (u & 0x80000000u) ? ~u : (u | 0x80000000u);
}
__device__ __forceinline__ float ord2f(unsigned o) {
    unsigned u = (o & 0x80000000u) ? (o & 0x7FFFFFFFu) : ~o;
    return __uint_as_float(u);
}

// ---------------- init per layer ----------------
__global__ void k_init() {
    int t = threadIdx.x;
    if (t < BQ) { g_sum[t] = 0.f; g_maxord[t] = 0u; }
}

// ---------------- h = A @ W + bias  (writes g_h) ----------------
// A is either external input (feature) or g_f (layer-1), selected by flag.
__global__ void k_gemm_h(const float* __restrict__ Aext, int use_gf,
                         const float* __restrict__ W,
                         const float* __restrict__ bias,
                         int K) {
    const float* __restrict__ A = use_gf ? g_f : Aext;
    __shared__ float As[32][33], Bs[32][33];
    int tx = threadIdx.x, ty = threadIdx.y;
    int tid = ty * 16 + tx;
    int row0 = blockIdx.y * 32, col0 = blockIdx.x * 32;
    float a00 = 0.f, a01 = 0.f, a10 = 0.f, a11 = 0.f;
    for (int k0 = 0; k0 < K; k0 += 32) {
        #pragma unroll
        for (int p = 0; p < 4; p++) {
            int idx = tid + p * 256;
            int r = idx >> 5, c = idx & 31;
            int ar = row0 + r, ac = k0 + c;
            As[r][c] = (ac < K) ? A[ar * K + ac] : 0.f;          // ar < 1024 always
            int br = k0 + r, bc = col0 + c;
            Bs[r][c] = (br < K && bc < MEMD) ? W[br * MEMD + bc] : 0.f;
        }
        __syncthreads();
        #pragma unroll
        for (int k = 0; k < 32; k++) {
            float x0 = As[ty][k], x1 = As[ty + 16][k];
            float y0 = Bs[k][tx], y1 = Bs[k][tx + 16];
            a00 = fmaf(x0, y0, a00); a01 = fmaf(x0, y1, a01);
            a10 = fmaf(x1, y0, a10); a11 = fmaf(x1, y1, a11);
        }
        __syncthreads();
    }
    int r0 = row0 + ty, r1 = row0 + ty + 16;
    int c0 = col0 + tx, c1 = col0 + tx + 16;
    if (c0 < MEMD) { g_h[r0 * MEMD + c0] = a00 + bias[c0]; g_h[r1 * MEMD + c0] = a10 + bias[c0]; }
    if (c1 < MEMD) { g_h[r0 * MEMD + c1] = a01 + bias[c1]; g_h[r1 * MEMD + c1] = a11 + bias[c1]; }
}

// ---------------- s = h @ [a1_w_top | a1_w_bot], a1_b folded into s_i half ----------------
// g_s layout: row r (= b*N + node), cols 0..63 = s_i + a1_b, cols 64..127 = s_j
__global__ void k_s(const float* __restrict__ a1w, const float* __restrict__ a1b) {
    __shared__ float As[32][33], Bs[32][33];
    int tx = threadIdx.x, ty = threadIdx.y;
    int tid = ty * 16 + tx;
    int row0 = blockIdx.y * 32, col0 = blockIdx.x * 32;   // col in [0,128)
    float a00 = 0.f, a01 = 0.f, a10 = 0.f, a11 = 0.f;
    for (int k0 = 0; k0 < MEMD; k0 += 32) {
        #pragma unroll
        for (int p = 0; p < 4; p++) {
            int idx = tid + p * 256;
            int r = idx >> 5, c = idx & 31;
            int ar = row0 + r, ac = k0 + c;
            As[r][c] = (ac < MEMD) ? g_h[ar * MEMD + ac] : 0.f;
            int bk = k0 + r, bc = col0 + c;
            float v = 0.f;
            if (bk < MEMD) {
                // cols 0..63 -> a1_w rows [0..MEM), cols 64..127 -> rows [MEM..2MEM)
                int src_row = (bc < HIDD) ? bk : (MEMD + bk);
                int src_col = (bc < HIDD) ? bc : (bc - HIDD);
                v = a1w[src_row * HIDD + src_col];
            }
            Bs[r][c] = v;
        }
        __syncthreads();
        #pragma unroll
        for (int k = 0; k < 32; k++) {
            float x0 = As[ty][k], x1 = As[ty + 16][k];
            float y0 = Bs[k][tx], y1 = Bs[k][tx + 16];
            a00 = fmaf(x0, y0, a00); a01 = fmaf(x0, y1, a01);
            a10 = fmaf(x1, y0, a10); a11 = fmaf(x1, y1, a11);
        }
        __syncthreads();
    }
    int r0 = row0 + ty, r1 = row0 + ty + 16;
    int c0 = col0 + tx, c1 = col0 + tx + 16;
    float bb0 = (c0 < HIDD) ? a1b[c0] : 0.f;
    float bb1 = (c1 < HIDD) ? a1b[c1] : 0.f;
    g_s[r0 * 128 + c0] = a00 + bb0;  g_s[r1 * 128 + c0] = a10 + bb0;
    g_s[r0 * 128 + c1] = a01 + bb1;  g_s[r1 * 128 + c1] = a11 + bb1;
}

// ---------------- e / masked logits + per-batch max ----------------
__global__ void k_e(const float* __restrict__ adj,
                    const float* __restrict__ a2w,
                    const float* __restrict__ a2b) {
    __shared__ float Si[32][HIDD + 1], Sj[32][HIDD + 1];
    __shared__ float Wv[HIDD];
    __shared__ float red[256];
    int tx = threadIdx.x, ty = threadIdx.y;
    int tid = ty * 16 + tx;
    int b = blockIdx.z;
    int i0 = blockIdx.y * 32, j0 = blockIdx.x * 32;
    if (tid < HIDD) Wv[tid] = a2w[tid];
    #pragma unroll
    for (int p = 0; p < 8; p++) {
        int idx = tid + p * 256;
        int r = idx >> 6, c = idx & 63;
        Si[r][c] = g_s[(b * NPTS + i0 + r) * 128 + c];
        Sj[r][c] = g_s[(b * NPTS + j0 + r) * 128 + 64 + c];
    }
    __syncthreads();
    float a00 = 0.f, a01 = 0.f, a10 = 0.f, a11 = 0.f;
    #pragma unroll 8
    for (int h = 0; h < HIDD; h++) {
        float w  = Wv[h];
        float s0 = Si[ty][h],      s1 = Si[ty + 16][h];
        float t0 = Sj[tx][h],      t1 = Sj[tx + 16][h];
        a00 = fmaf(fmaxf(s0 + t0, 0.f), w, a00);
        a01 = fmaf(fmaxf(s0 + t1, 0.f), w, a01);
        a10 = fmaf(fmaxf(s1 + t0, 0.f), w, a10);
        a11 = fmaf(fmaxf(s1 + t1, 0.f), w, a11);
    }
    float ab = a2b[0];
    float m = -3.0e38f;
    float acc[2][2] = {{a00, a01}, {a10, a11}};
    #pragma unroll
    for (int di = 0; di < 2; di++) {
        #pragma unroll
        for (int dj = 0; dj < 2; dj++) {
            int i = i0 + ty + di * 16;
            int j = j0 + tx + dj * 16;
            float e = acc[di][dj] + ab;
            e = (e > 0.f) ? e : NEG * e;
            float a = adj[(b * NPTS + i) * NPTS + j];
            float lg = e * a + (1.f - a) * (-1e30f);
            g_u[b * NN + i * NPTS + j] = lg;
            m = fmaxf(m, lg);
        }
    }
    red[tid] = m;
    __syncthreads();
    for (int s = 128; s > 0; s >>= 1) {
        if (tid < s) red[tid] = fmaxf(red[tid], red[tid + s]);
        __syncthreads();
    }
    if (tid == 0) atomicMax(&g_maxord[b], f2ord(red[0]));
}

// ---------------- u = exp(logit - max), per-batch sum ----------------
__global__ void k_exp() {
    __shared__ float red[256];
    int b = blockIdx.y;
    int idx = blockIdx.x * 256 + threadIdx.x;
    float mx = ord2f(g_maxord[b]);
    float v = g_u[b * NN + idx];
    float u = __expf(v - mx);           // masked (-1e30) underflows to exactly 0
    g_u[b * NN + idx] = u;
    red[threadIdx.x] = u;
    __syncthreads();
    for (int s = 128; s > 0; s >>= 1) {
        if (threadIdx.x < s) red[threadIdx.x] += red[threadIdx.x + s];
        __syncthreads();
    }
    if (threadIdx.x == 0) atomicAdd(&g_sum[b], red[0]);
}

// ---------------- out = (U @ h) / sum  (batched) ----------------
__global__ void k_out(float* __restrict__ out) {
    __shared__ float As[32][33], Bs[32][33];
    int tx = threadIdx.x, ty = threadIdx.y;
    int tid = ty * 16 + tx;
    int b = blockIdx.z;
    const float* __restrict__ A  = g_u + b * NN;           // 512 x 512
    const float* __restrict__ Bm = g_h + b * NPTS * MEMD;  // 512 x 300
    float inv = 1.f / g_sum[b];
    int row0 = blockIdx.y * 32, col0 = blockIdx.x * 32;
    float a00 = 0.f, a01 = 0.f, a10 = 0.f, a11 = 0.f;
    for (int k0 = 0; k0 < NPTS; k0 += 32) {
        #pragma unroll
        for (int p = 0; p < 4; p++) {
            int idx = tid + p * 256;
            int r = idx >> 5, c = idx & 31;
            As[r][c] = A[(row0 + r) * NPTS + (k0 + c)];
            int bc = col0 + c;
            Bs[r][c] = (bc < MEMD) ? Bm[(k0 + r) * MEMD + bc] : 0.f;
        }
        __syncthreads();
        #pragma unroll
        for (int k = 0; k < 32; k++) {
            float x0 = As[ty][k], x1 = As[ty + 16][k];
            float y0 = Bs[k][tx], y1 = Bs[k][tx + 16];
            a00 = fmaf(x0, y0, a00); a01 = fmaf(x0, y1, a01);
            a10 = fmaf(x1, y0, a10); a11 = fmaf(x1, y1, a11);
        }
        __syncthreads();
    }
    int r0 = row0 + ty, r1 = row0 + ty + 16;
    int c0 = col0 + tx, c1 = col0 + tx + 16;
    float* O = out + b * NPTS * MEMD;
    if (c0 < MEMD) { O[r0 * MEMD + c0] = a00 * inv; O[r1 * MEMD + c0] = a10 * inv; }
    if (c1 < MEMD) { O[r0 * MEMD + c1] = a01 * inv; O[r1 * MEMD + c1] = a11 * inv; }
}

// ---------------- host ----------------
extern "C" void kernel_launch(void* const* d_in, const int* in_sizes, int n_in,
                              void* d_out, int out_size) {
    const float* feature = (const float*)d_in[0];
    const float* adj     = (const float*)d_in[1];
    const float* w0      = (const float*)d_in[2];
    const float* b0      = (const float*)d_in[3];
    const float* w1      = (const float*)d_in[4];
    const float* b1      = (const float*)d_in[5];
    const float* a1w     = (const float*)d_in[6];
    const float* a1b     = (const float*)d_in[7];
    const float* a2w     = (const float*)d_in[8];
    const float* a2b     = (const float*)d_in[9];
    float* out = (float*)d_out;

    dim3 blk(16, 16);
    dim3 g_h_grid((MEMD + 31) / 32, ROWS / 32);       // 10 x 32
    dim3 g_s_grid(128 / 32, ROWS / 32);               // 4 x 32
    dim3 g_e_grid(NPTS / 32, NPTS / 32, BQ);          // 16 x 16 x 2
    dim3 g_exp_grid(NN / 256, BQ);                    // 1024 x 2
    dim3 g_out_grid((MEMD + 31) / 32, NPTS / 32, BQ); // 10 x 16 x 2

    // ---- layer 0 ----
    k_init<<<1, 32>>>();
    k_gemm_h<<<g_h_grid, blk>>>(feature, 0, w0, b0, INDIM);
    k_s<<<g_s_grid, blk>>>(a1w, a1b);
    k_e<<<g_e_grid, blk>>>(adj, a2w, a2b);
    k_exp<<<g_exp_grid, 256>>>();
    {
        // write layer-0 result into g_f via k_out pointing at it
        float* fptr;
        cudaGetSymbolAddress((void**)&fptr, g_f);
        k_out<<<g_out_grid, blk>>>(fptr);
    }

    // ---- layer 1 ----
    k_init<<<1, 32>>>();
    k_gemm_h<<<g_h_grid, blk>>>(nullptr, 1, w1, b1, MEMD);
    k_s<<<g_s_grid, blk>>>(a1w, a1b);
    k_e<<<g_e_grid, blk>>>(adj, a2w, a2b);
    k_exp<<<g_exp_grid, 256>>>();
    k_out<<<g_out_grid, blk>>>(out);
}

// round 3
// speedup vs baseline: 1.2132x; 1.2132x over previous
#include <cuda_runtime.h>

#define BQ 2
#define NPTS 512
#define INDIM 512
#define MEMD 300
#define HIDD 64
#define NEG 0.01f
#define NN (NPTS*NPTS)
#define ROWS (BQ*NPTS)   // 1024
#define AST 36           // smem tile stride (mult of 4 for vec LDS)

typedef unsigned long long ull;

// ---------------- scratch ----------------
__device__ float g_h[ROWS*MEMD];
__device__ float g_s[ROWS*2*HIDD];
__device__ float g_u[BQ*NN];
__device__ float g_f[ROWS*MEMD];
__device__ float g_sum[BQ];
__device__ unsigned g_maxord[BQ];

__device__ __forceinline__ unsigned f2ord(float f) {
    unsigned u = __float_as_uint(f);
    return (u & 0x80000000u) ? ~u : (u | 0x80000000u);
}
__device__ __forceinline__ float ord2f(unsigned o) {
    unsigned u = (o & 0x80000000u) ? (o & 0x7FFFFFFFu) : ~o;
    return __uint_as_float(u);
}

// ---------------- f32x2 helpers ----------------
__device__ __forceinline__ ull dup2(float x) {
    ull r; asm("mov.b64 %0, {%1,%1};" : "=l"(r) : "f"(x)); return r;
}
__device__ __forceinline__ void ffma2(ull& d, ull a, ull b) {
    asm("fma.rn.f32x2 %0, %1, %2, %0;" : "+l"(d) : "l"(a), "l"(b));
}
__device__ __forceinline__ float2 unpk(ull v) {
    float2 r; asm("mov.b64 {%0,%1}, %2;" : "=f"(r.x), "=f"(r.y) : "l"(v)); return r;
}

// ============ h = A @ W + bias  (32x32 tile, 128 thr, 4x2 micro, f32x2) ============
__global__ void k_gemm_h(const float* __restrict__ Aext, int use_gf,
                         const float* __restrict__ W,
                         const float* __restrict__ bias, int K) {
    const float* __restrict__ A = use_gf ? g_f : Aext;
    __shared__ float As[16][AST];   // [k][row]
    __shared__ float Bs[16][AST];   // [k][col]
    int tx = threadIdx.x, ty = threadIdx.y;       // 16 x 8
    int tid = ty * 16 + tx;
    int row0 = blockIdx.y * 32, col0 = blockIdx.x * 32;
    if (blockIdx.x == 0 && blockIdx.y == 0 && tid < BQ) {
        g_sum[tid] = 0.f; g_maxord[tid] = 0u;     // reset for this layer's softmax
    }
    ull acc00 = 0, acc01 = 0, acc10 = 0, acc11 = 0;
    int ty4 = ty * 4, tx2 = tx * 2;
    for (int k0 = 0; k0 < K; k0 += 16) {
        #pragma unroll
        for (int p = 0; p < 4; p++) {
            int idx = tid + p * 128;
            int kk = idx & 15, r = idx >> 4;
            int ac = k0 + kk;
            As[kk][r] = (ac < K) ? A[(row0 + r) * K + ac] : 0.f;
            int c = idx & 31, kb = idx >> 5;
            int bc = col0 + c, bk = k0 + kb;
            Bs[kb][c] = (bk < K && bc < MEMD) ? W[bk * MEMD + bc] : 0.f;
        }
        __syncthreads();
        #pragma unroll
        for (int k = 0; k < 16; k++) {
            ull a01 = *(const ull*)&As[k][ty4];
            ull a23 = *(const ull*)&As[k][ty4 + 2];
            float2 b = *(const float2*)&Bs[k][tx2];
            ull b0 = dup2(b.x), b1 = dup2(b.y);
            ffma2(acc00, a01, b0); ffma2(acc01, a23, b0);
            ffma2(acc10, a01, b1); ffma2(acc11, a23, b1);
        }
        __syncthreads();
    }
    int c0 = col0 + tx2;
    if (c0 < MEMD) {
        float2 bb = *(const float2*)&bias[c0];
        float2 j0p0 = unpk(acc00), j0p1 = unpk(acc01);
        float2 j1p0 = unpk(acc10), j1p1 = unpk(acc11);
        int r = row0 + ty4;
        float2 v;
        v.x = j0p0.x + bb.x; v.y = j1p0.x + bb.y; *(float2*)&g_h[(r+0)*MEMD + c0] = v;
        v.x = j0p0.y + bb.x; v.y = j1p0.y + bb.y; *(float2*)&g_h[(r+1)*MEMD + c0] = v;
        v.x = j0p1.x + bb.x; v.y = j1p1.x + bb.y; *(float2*)&g_h[(r+2)*MEMD + c0] = v;
        v.x = j0p1.y + bb.x; v.y = j1p1.y + bb.y; *(float2*)&g_h[(r+3)*MEMD + c0] = v;
    }
}

// ============ s = h @ [a1w_top | a1w_bot] (+a1b on s_i half) ============
__global__ void k_s(const float* __restrict__ a1w, const float* __restrict__ a1b) {
    __shared__ float As[16][AST];
    __shared__ float Bs[16][AST];
    int tx = threadIdx.x, ty = threadIdx.y;
    int tid = ty * 16 + tx;
    int row0 = blockIdx.y * 32, col0 = blockIdx.x * 32;   // col0 in [0,128)
    ull acc00 = 0, acc01 = 0, acc10 = 0, acc11 = 0;
    int ty4 = ty * 4, tx2 = tx * 2;
    for (int k0 = 0; k0 < MEMD; k0 += 16) {
        #pragma unroll
        for (int p = 0; p < 4; p++) {
            int idx = tid + p * 128;
            int kk = idx & 15, r = idx >> 4;
            int ac = k0 + kk;
            As[kk][r] = (ac < MEMD) ? g_h[(row0 + r) * MEMD + ac] : 0.f;
            int c = idx & 31, kb = idx >> 5;
            int bc = col0 + c, bk = k0 + kb;
            float v = 0.f;
            if (bk < MEMD)
                v = (bc < HIDD) ? a1w[bk * HIDD + bc]
                                : a1w[(MEMD + bk) * HIDD + (bc - HIDD)];
            Bs[kb][c] = v;
        }
        __syncthreads();
        #pragma unroll
        for (int k = 0; k < 16; k++) {
            ull a01 = *(const ull*)&As[k][ty4];
            ull a23 = *(const ull*)&As[k][ty4 + 2];
            float2 b = *(const float2*)&Bs[k][tx2];
            ull b0 = dup2(b.x), b1 = dup2(b.y);
            ffma2(acc00, a01, b0); ffma2(acc01, a23, b0);
            ffma2(acc10, a01, b1); ffma2(acc11, a23, b1);
        }
        __syncthreads();
    }
    int c0 = col0 + tx2;
    float2 bb = make_float2(0.f, 0.f);
    if (c0 < HIDD) bb = *(const float2*)&a1b[c0];
    float2 j0p0 = unpk(acc00), j0p1 = unpk(acc01);
    float2 j1p0 = unpk(acc10), j1p1 = unpk(acc11);
    int r = row0 + ty4;
    float2 v;
    v.x = j0p0.x + bb.x; v.y = j1p0.x + bb.y; *(float2*)&g_s[(r+0)*128 + c0] = v;
    v.x = j0p0.y + bb.x; v.y = j1p0.y + bb.y; *(float2*)&g_s[(r+1)*128 + c0] = v;
    v.x = j0p1.x + bb.x; v.y = j1p1.x + bb.y; *(float2*)&g_s[(r+2)*128 + c0] = v;
    v.x = j0p1.y + bb.x; v.y = j1p1.y + bb.y; *(float2*)&g_s[(r+3)*128 + c0] = v;
}

// ============ e / masked logits + per-batch max (64x64 tile, 256 thr, 4x4) ============
__global__ void k_e(const float* __restrict__ adj,
                    const float* __restrict__ a2w,
                    const float* __restrict__ a2b) {
    __shared__ float Si[64][68];     // [h][i_local]
    __shared__ float Sj[64][68];     // [h][j_local]
    __shared__ float Wv[64];
    __shared__ float red[256];
    int tx = threadIdx.x, ty = threadIdx.y;      // 16 x 16
    int tid = ty * 16 + tx;
    int b = blockIdx.z;
    int i0 = blockIdx.y * 64, j0 = blockIdx.x * 64;
    if (tid < 64) Wv[tid] = a2w[tid];
    #pragma unroll
    for (int p = 0; p < 16; p++) {
        int idx = tid + p * 256;
        int h = idx & 63, r = idx >> 6;
        Si[h][r] = g_s[(b * NPTS + i0 + r) * 128 + h];
        Sj[h][r] = g_s[(b * NPTS + j0 + r) * 128 + 64 + h];
    }
    __syncthreads();
    float acc[4][4] = {};
    int ty4 = ty * 4, tx4 = tx * 4;
    #pragma unroll 4
    for (int h = 0; h < 64; h++) {
        float w = Wv[h];
        float4 si = *(const float4*)&Si[h][ty4];
        float4 sj = *(const float4*)&Sj[h][tx4];
        float siv[4] = {si.x, si.y, si.z, si.w};
        float sjv[4] = {sj.x, sj.y, sj.z, sj.w};
        #pragma unroll
        for (int di = 0; di < 4; di++)
            #pragma unroll
            for (int dj = 0; dj < 4; dj++)
                acc[di][dj] = fmaf(fmaxf(siv[di] + sjv[dj], 0.f), w, acc[di][dj]);
    }
    float ab = a2b[0];
    float m = -3.0e38f;
    #pragma unroll
    for (int di = 0; di < 4; di++) {
        int i = i0 + ty4 + di;
        float4 av = *(const float4*)&adj[(b * NPTS + i) * NPTS + j0 + tx4];
        float avv[4] = {av.x, av.y, av.z, av.w};
        float o[4];
        #pragma unroll
        for (int dj = 0; dj < 4; dj++) {
            float e = acc[di][dj] + ab;
            e = (e > 0.f) ? e : NEG * e;
            float lg = e * avv[dj] + (1.f - avv[dj]) * (-1e30f);
            o[dj] = lg;
            m = fmaxf(m, lg);
        }
        float4 ov = make_float4(o[0], o[1], o[2], o[3]);
        *(float4*)&g_u[b * NN + i * NPTS + j0 + tx4] = ov;
    }
    red[tid] = m;
    __syncthreads();
    for (int s = 128; s > 0; s >>= 1) {
        if (tid < s) red[tid] = fmaxf(red[tid], red[tid + s]);
        __syncthreads();
    }
    if (tid == 0) atomicMax(&g_maxord[b], f2ord(red[0]));
}

// ============ u = exp(logit - max), per-batch sum (float4) ============
__global__ void k_exp() {
    __shared__ float red[256];
    int b = blockIdx.y;
    int idx = (blockIdx.x * 256 + threadIdx.x) * 4;
    float mx = ord2f(g_maxord[b]);
    float4 v = *(float4*)&g_u[b * NN + idx];
    v.x = __expf(v.x - mx); v.y = __expf(v.y - mx);
    v.z = __expf(v.z - mx); v.w = __expf(v.w - mx);
    *(float4*)&g_u[b * NN + idx] = v;
    red[threadIdx.x] = (v.x + v.y) + (v.z + v.w);
    __syncthreads();
    for (int s = 128; s > 0; s >>= 1) {
        if (threadIdx.x < s) red[threadIdx.x] += red[threadIdx.x + s];
        __syncthreads();
    }
    if (threadIdx.x == 0) atomicAdd(&g_sum[b], red[0]);
}

// ============ out = (U @ h) / sum (32x32 tile, 128 thr, 4x2 micro, f32x2) ============
__global__ void k_out(float* __restrict__ out_ext, int to_gf) {
    float* __restrict__ Ob = to_gf ? g_f : out_ext;
    __shared__ float As[16][AST];
    __shared__ float Bs[16][AST];
    int tx = threadIdx.x, ty = threadIdx.y;
    int tid = ty * 16 + tx;
    int b = blockIdx.z;
    const float* __restrict__ A  = g_u + b * NN;            // 512 x 512
    const float* __restrict__ Bm = g_h + b * NPTS * MEMD;   // 512 x 300
    float inv = 1.f / g_sum[b];
    int row0 = blockIdx.y * 32, col0 = blockIdx.x * 32;
    ull acc00 = 0, acc01 = 0, acc10 = 0, acc11 = 0;
    int ty4 = ty * 4, tx2 = tx * 2;
    for (int k0 = 0; k0 < NPTS; k0 += 16) {
        #pragma unroll
        for (int p = 0; p < 4; p++) {
            int idx = tid + p * 128;
            int kk = idx & 15, r = idx >> 4;
            As[kk][r] = A[(row0 + r) * NPTS + k0 + kk];
            int c = idx & 31, kb = idx >> 5;
            int bc = col0 + c;
            Bs[kb][c] = (bc < MEMD) ? Bm[(k0 + kb) * MEMD + bc] : 0.f;
        }
        __syncthreads();
        #pragma unroll
        for (int k = 0; k < 16; k++) {
            ull a01 = *(const ull*)&As[k][ty4];
            ull a23 = *(const ull*)&As[k][ty4 + 2];
            float2 bv = *(const float2*)&Bs[k][tx2];
            ull b0 = dup2(bv.x), b1 = dup2(bv.y);
            ffma2(acc00, a01, b0); ffma2(acc01, a23, b0);
            ffma2(acc10, a01, b1); ffma2(acc11, a23, b1);
        }
        __syncthreads();
    }
    int c0 = col0 + tx2;
    if (c0 < MEMD) {
        float2 j0p0 = unpk(acc00), j0p1 = unpk(acc01);
        float2 j1p0 = unpk(acc10), j1p1 = unpk(acc11);
        int r = row0 + ty4;
        float* O = Ob + b * NPTS * MEMD;
        float2 v;
        v.x = j0p0.x * inv; v.y = j1p0.x * inv; *(float2*)&O[(r+0)*MEMD + c0] = v;
        v.x = j0p0.y * inv; v.y = j1p0.y * inv; *(float2*)&O[(r+1)*MEMD + c0] = v;
        v.x = j0p1.x * inv; v.y = j1p1.x * inv; *(float2*)&O[(r+2)*MEMD + c0] = v;
        v.x = j0p1.y * inv; v.y = j1p1.y * inv; *(float2*)&O[(r+3)*MEMD + c0] = v;
    }
}

// ---------------- host ----------------
extern "C" void kernel_launch(void* const* d_in, const int* in_sizes, int n_in,
                              void* d_out, int out_size) {
    const float* feature = (const float*)d_in[0];
    const float* adj     = (const float*)d_in[1];
    const float* w0      = (const float*)d_in[2];
    const float* b0      = (const float*)d_in[3];
    const float* w1      = (const float*)d_in[4];
    const float* b1      = (const float*)d_in[5];
    const float* a1w     = (const float*)d_in[6];
    const float* a1b     = (const float*)d_in[7];
    const float* a2w     = (const float*)d_in[8];
    const float* a2b     = (const float*)d_in[9];
    float* out = (float*)d_out;

    dim3 b128(16, 8), b256(16, 16);
    dim3 gh(10, 32);          // 300/32 x 1024/32
    dim3 gs(4, 32);           // 128/32 x 1024/32
    dim3 ge(8, 8, BQ);        // 512/64 x 512/64
    dim3 gx(NN / 1024, BQ);   // float4 per thread
    dim3 go(10, 16, BQ);      // 300/32 x 512/32

    // ---- layer 0 ----
    k_gemm_h<<<gh, b128>>>(feature, 0, w0, b0, INDIM);
    k_s<<<gs, b128>>>(a1w, a1b);
    k_e<<<ge, b256>>>(adj, a2w, a2b);
    k_exp<<<gx, 256>>>();
    k_out<<<go, b128>>>(out, 1);      // -> g_f

    // ---- layer 1 ----
    k_gemm_h<<<gh, b128>>>(nullptr, 1, w1, b1, MEMD);
    k_s<<<gs, b128>>>(a1w, a1b);
    k_e<<<ge, b256>>>(adj, a2w, a2b);
    k_exp<<<gx, 256>>>();
    k_out<<<go, b128>>>(out, 0);      // -> d_out
}

// round 5
// speedup vs baseline: 1.2134x; 1.0002x over previous
#include <cuda_runtime.h>

#define BQ 2
#define NPTS 512
#define INDIM 512
#define MEMD 300
#define HIDD 64
#define NEG 0.01f
#define NN (NPTS*NPTS)
#define ROWS (BQ*NPTS)   // 1024
#define AST 36           // smem tile stride (mult of 4 for vec LDS)

typedef unsigned long long ull;

// ---------------- scratch ----------------
__device__ float g_h[ROWS*MEMD];
__device__ float g_s[ROWS*2*HIDD];
__device__ float g_u[BQ*NN];
__device__ float g_f[ROWS*MEMD];
__device__ float g_sum[BQ];
__device__ unsigned g_maxord[BQ];

__device__ __forceinline__ unsigned f2ord(float f) {
    unsigned u = __float_as_uint(f);
    return (u & 0x80000000u) ? ~u : (u | 0x80000000u);
}
__device__ __forceinline__ float ord2f(unsigned o) {
    unsigned u = (o & 0x80000000u) ? (o & 0x7FFFFFFFu) : ~o;
    return __uint_as_float(u);
}

// ---------------- f32x2 helpers ----------------
__device__ __forceinline__ ull dup2(float x) {
    ull r; asm("mov.b64 %0, {%1,%1};" : "=l"(r) : "f"(x)); return r;
}
__device__ __forceinline__ void ffma2(ull& d, ull a, ull b) {
    asm("fma.rn.f32x2 %0, %1, %2, %0;" : "+l"(d) : "l"(a), "l"(b));
}
__device__ __forceinline__ float2 unpk(ull v) {
    float2 r; asm("mov.b64 {%0,%1}, %2;" : "=f"(r.x), "=f"(r.y) : "l"(v)); return r;
}

// ============ h = A @ W + bias  (32x32 tile, 128 thr, 4x2 micro, f32x2) ============
__global__ void k_gemm_h(const float* __restrict__ Aext, int use_gf,
                         const float* __restrict__ W,
                         const float* __restrict__ bias, int K) {
    const float* __restrict__ A = use_gf ? g_f : Aext;
    __shared__ float As[16][AST];   // [k][row]
    __shared__ float Bs[16][AST];   // [k][col]
    int tx = threadIdx.x, ty = threadIdx.y;       // 16 x 8
    int tid = ty * 16 + tx;
    int row0 = blockIdx.y * 32, col0 = blockIdx.x * 32;
    if (blockIdx.x == 0 && blockIdx.y == 0 && tid < BQ) {
        g_sum[tid] = 0.f; g_maxord[tid] = 0u;     // reset for this layer's softmax
    }
    ull acc00 = 0, acc01 = 0, acc10 = 0, acc11 = 0;
    int ty4 = ty * 4, tx2 = tx * 2;
    for (int k0 = 0; k0 < K; k0 += 16) {
        #pragma unroll
        for (int p = 0; p < 4; p++) {
            int idx = tid + p * 128;
            int kk = idx & 15, r = idx >> 4;
            int ac = k0 + kk;
            As[kk][r] = (ac < K) ? A[(row0 + r) * K + ac] : 0.f;
            int c = idx & 31, kb = idx >> 5;
            int bc = col0 + c, bk = k0 + kb;
            Bs[kb][c] = (bk < K && bc < MEMD) ? W[bk * MEMD + bc] : 0.f;
        }
        __syncthreads();
        #pragma unroll
        for (int k = 0; k < 16; k++) {
            ull a01 = *(const ull*)&As[k][ty4];
            ull a23 = *(const ull*)&As[k][ty4 + 2];
            float2 b = *(const float2*)&Bs[k][tx2];
            ull b0 = dup2(b.x), b1 = dup2(b.y);
            ffma2(acc00, a01, b0); ffma2(acc01, a23, b0);
            ffma2(acc10, a01, b1); ffma2(acc11, a23, b1);
        }
        __syncthreads();
    }
    int c0 = col0 + tx2;
    if (c0 < MEMD) {
        float2 bb = *(const float2*)&bias[c0];
        float2 j0p0 = unpk(acc00), j0p1 = unpk(acc01);
        float2 j1p0 = unpk(acc10), j1p1 = unpk(acc11);
        int r = row0 + ty4;
        float2 v;
        v.x = j0p0.x + bb.x; v.y = j1p0.x + bb.y; *(float2*)&g_h[(r+0)*MEMD + c0] = v;
        v.x = j0p0.y + bb.x; v.y = j1p0.y + bb.y; *(float2*)&g_h[(r+1)*MEMD + c0] = v;
        v.x = j0p1.x + bb.x; v.y = j1p1.x + bb.y; *(float2*)&g_h[(r+2)*MEMD + c0] = v;
        v.x = j0p1.y + bb.x; v.y = j1p1.y + bb.y; *(float2*)&g_h[(r+3)*MEMD + c0] = v;
    }
}

// ============ s = h @ [a1w_top | a1w_bot] (+a1b on s_i half) ============
__global__ void k_s(const float* __restrict__ a1w, const float* __restrict__ a1b) {
    __shared__ float As[16][AST];
    __shared__ float Bs[16][AST];
    int tx = threadIdx.x, ty = threadIdx.y;
    int tid = ty * 16 + tx;
    int row0 = blockIdx.y * 32, col0 = blockIdx.x * 32;   // col0 in [0,128)
    ull acc00 = 0, acc01 = 0, acc10 = 0, acc11 = 0;
    int ty4 = ty * 4, tx2 = tx * 2;
    for (int k0 = 0; k0 < MEMD; k0 += 16) {
        #pragma unroll
        for (int p = 0; p < 4; p++) {
            int idx = tid + p * 128;
            int kk = idx & 15, r = idx >> 4;
            int ac = k0 + kk;
            As[kk][r] = (ac < MEMD) ? g_h[(row0 + r) * MEMD + ac] : 0.f;
            int c = idx & 31, kb = idx >> 5;
            int bc = col0 + c, bk = k0 + kb;
            float v = 0.f;
            if (bk < MEMD)
                v = (bc < HIDD) ? a1w[bk * HIDD + bc]
                                : a1w[(MEMD + bk) * HIDD + (bc - HIDD)];
            Bs[kb][c] = v;
        }
        __syncthreads();
        #pragma unroll
        for (int k = 0; k < 16; k++) {
            ull a01 = *(const ull*)&As[k][ty4];
            ull a23 = *(const ull*)&As[k][ty4 + 2];
            float2 b = *(const float2*)&Bs[k][tx2];
            ull b0 = dup2(b.x), b1 = dup2(b.y);
            ffma2(acc00, a01, b0); ffma2(acc01, a23, b0);
            ffma2(acc10, a01, b1); ffma2(acc11, a23, b1);
        }
        __syncthreads();
    }
    int c0 = col0 + tx2;
    float2 bb = make_float2(0.f, 0.f);
    if (c0 < HIDD) bb = *(const float2*)&a1b[c0];
    float2 j0p0 = unpk(acc00), j0p1 = unpk(acc01);
    float2 j1p0 = unpk(acc10), j1p1 = unpk(acc11);
    int r = row0 + ty4;
    float2 v;
    v.x = j0p0.x + bb.x; v.y = j1p0.x + bb.y; *(float2*)&g_s[(r+0)*128 + c0] = v;
    v.x = j0p0.y + bb.x; v.y = j1p0.y + bb.y; *(float2*)&g_s[(r+1)*128 + c0] = v;
    v.x = j0p1.x + bb.x; v.y = j1p1.x + bb.y; *(float2*)&g_s[(r+2)*128 + c0] = v;
    v.x = j0p1.y + bb.x; v.y = j1p1.y + bb.y; *(float2*)&g_s[(r+3)*128 + c0] = v;
}

// ============ e / masked logits + per-batch max (64x64 tile, 256 thr, 4x4) ============
__global__ void k_e(const float* __restrict__ adj,
                    const float* __restrict__ a2w,
                    const float* __restrict__ a2b) {
    __shared__ float Si[64][68];     // [h][i_local]
    __shared__ float Sj[64][68];     // [h][j_local]
    __shared__ float Wv[64];
    __shared__ float red[256];
    int tx = threadIdx.x, ty = threadIdx.y;      // 16 x 16
    int tid = ty * 16 + tx;
    int b = blockIdx.z;
    int i0 = blockIdx.y * 64, j0 = blockIdx.x * 64;
    if (tid < 64) Wv[tid] = a2w[tid];
    #pragma unroll
    for (int p = 0; p < 16; p++) {
        int idx = tid + p * 256;
        int h = idx & 63, r = idx >> 6;
        Si[h][r] = g_s[(b * NPTS + i0 + r) * 128 + h];
        Sj[h][r] = g_s[(b * NPTS + j0 + r) * 128 + 64 + h];
    }
    __syncthreads();
    float acc[4][4] = {};
    int ty4 = ty * 4, tx4 = tx * 4;
    #pragma unroll 4
    for (int h = 0; h < 64; h++) {
        float w = Wv[h];
        float4 si = *(const float4*)&Si[h][ty4];
        float4 sj = *(const float4*)&Sj[h][tx4];
        float siv[4] = {si.x, si.y, si.z, si.w};
        float sjv[4] = {sj.x, sj.y, sj.z, sj.w};
        #pragma unroll
        for (int di = 0; di < 4; di++)
            #pragma unroll
            for (int dj = 0; dj < 4; dj++)
                acc[di][dj] = fmaf(fmaxf(siv[di] + sjv[dj], 0.f), w, acc[di][dj]);
    }
    float ab = a2b[0];
    float m = -3.0e38f;
    #pragma unroll
    for (int di = 0; di < 4; di++) {
        int i = i0 + ty4 + di;
        float4 av = *(const float4*)&adj[(b * NPTS + i) * NPTS + j0 + tx4];
        float avv[4] = {av.x, av.y, av.z, av.w};
        float o[4];
        #pragma unroll
        for (int dj = 0; dj < 4; dj++) {
            float e = acc[di][dj] + ab;
            e = (e > 0.f) ? e : NEG * e;
            float lg = e * avv[dj] + (1.f - avv[dj]) * (-1e30f);
            o[dj] = lg;
            m = fmaxf(m, lg);
        }
        float4 ov = make_float4(o[0], o[1], o[2], o[3]);
        *(float4*)&g_u[b * NN + i * NPTS + j0 + tx4] = ov;
    }
    red[tid] = m;
    __syncthreads();
    for (int s = 128; s > 0; s >>= 1) {
        if (tid < s) red[tid] = fmaxf(red[tid], red[tid + s]);
        __syncthreads();
    }
    if (tid == 0) atomicMax(&g_maxord[b], f2ord(red[0]));
}

// ============ u = exp(logit - max), per-batch sum (float4) ============
__global__ void k_exp() {
    __shared__ float red[256];
    int b = blockIdx.y;
    int idx = (blockIdx.x * 256 + threadIdx.x) * 4;
    float mx = ord2f(g_maxord[b]);
    float4 v = *(float4*)&g_u[b * NN + idx];
    v.x = __expf(v.x - mx); v.y = __expf(v.y - mx);
    v.z = __expf(v.z - mx); v.w = __expf(v.w - mx);
    *(float4*)&g_u[b * NN + idx] = v;
    red[threadIdx.x] = (v.x + v.y) + (v.z + v.w);
    __syncthreads();
    for (int s = 128; s > 0; s >>= 1) {
        if (threadIdx.x < s) red[threadIdx.x] += red[threadIdx.x + s];
        __syncthreads();
    }
    if (threadIdx.x == 0) atomicAdd(&g_sum[b], red[0]);
}

// ============ out = (U @ h) / sum (32x32 tile, 128 thr, 4x2 micro, f32x2) ============
__global__ void k_out(float* __restrict__ out_ext, int to_gf) {
    float* __restrict__ Ob = to_gf ? g_f : out_ext;
    __shared__ float As[16][AST];
    __shared__ float Bs[16][AST];
    int tx = threadIdx.x, ty = threadIdx.y;
    int tid = ty * 16 + tx;
    int b = blockIdx.z;
    const float* __restrict__ A  = g_u + b * NN;            // 512 x 512
    const float* __restrict__ Bm = g_h + b * NPTS * MEMD;   // 512 x 300
    float inv = 1.f / g_sum[b];
    int row0 = blockIdx.y * 32, col0 = blockIdx.x * 32;
    ull acc00 = 0, acc01 = 0, acc10 = 0, acc11 = 0;
    int ty4 = ty * 4, tx2 = tx * 2;
    for (int k0 = 0; k0 < NPTS; k0 += 16) {
        #pragma unroll
        for (int p = 0; p < 4; p++) {
            int idx = tid + p * 128;
            int kk = idx & 15, r = idx >> 4;
            As[kk][r] = A[(row0 + r) * NPTS + k0 + kk];
            int c = idx & 31, kb = idx >> 5;
            int bc = col0 + c;
            Bs[kb][c] = (bc < MEMD) ? Bm[(k0 + kb) * MEMD + bc] : 0.f;
        }
        __syncthreads();
        #pragma unroll
        for (int k = 0; k < 16; k++) {
            ull a01 = *(const ull*)&As[k][ty4];
            ull a23 = *(const ull*)&As[k][ty4 + 2];
            float2 bv = *(const float2*)&Bs[k][tx2];
            ull b0 = dup2(bv.x), b1 = dup2(bv.y);
            ffma2(acc00, a01, b0); ffma2(acc01, a23, b0);
            ffma2(acc10, a01, b1); ffma2(acc11, a23, b1);
        }
        __syncthreads();
    }
    int c0 = col0 + tx2;
    if (c0 < MEMD) {
        float2 j0p0 = unpk(acc00), j0p1 = unpk(acc01);
        float2 j1p0 = unpk(acc10), j1p1 = unpk(acc11);
        int r = row0 + ty4;
        float* O = Ob + b * NPTS * MEMD;
        float2 v;
        v.x = j0p0.x * inv; v.y = j1p0.x * inv; *(float2*)&O[(r+0)*MEMD + c0] = v;
        v.x = j0p0.y * inv; v.y = j1p0.y * inv; *(float2*)&O[(r+1)*MEMD + c0] = v;
        v.x = j0p1.x * inv; v.y = j1p1.x * inv; *(float2*)&O[(r+2)*MEMD + c0] = v;
        v.x = j0p1.y * inv; v.y = j1p1.y * inv; *(float2*)&O[(r+3)*MEMD + c0] = v;
    }
}

// ---------------- host ----------------
extern "C" void kernel_launch(void* const* d_in, const int* in_sizes, int n_in,
                              void* d_out, int out_size) {
    const float* feature = (const float*)d_in[0];
    const float* adj     = (const float*)d_in[1];
    const float* w0      = (const float*)d_in[2];
    const float* b0      = (const float*)d_in[3];
    const float* w1      = (const float*)d_in[4];
    const float* b1      = (const float*)d_in[5];
    const float* a1w     = (const float*)d_in[6];
    const float* a1b     = (const float*)d_in[7];
    const float* a2w     = (const float*)d_in[8];
    const float* a2b     = (const float*)d_in[9];
    float* out = (float*)d_out;

    dim3 b128(16, 8), b256(16, 16);
    dim3 gh(10, 32);          // 300/32 x 1024/32
    dim3 gs(4, 32);           // 128/32 x 1024/32
    dim3 ge(8, 8, BQ);        // 512/64 x 512/64
    dim3 gx(NN / 1024, BQ);   // float4 per thread
    dim3 go(10, 16, BQ);      // 300/32 x 512/32

    // ---- layer 0 ----
    k_gemm_h<<<gh, b128>>>(feature, 0, w0, b0, INDIM);
    k_s<<<gs, b128>>>(a1w, a1b);
    k_e<<<ge, b256>>>(adj, a2w, a2b);
    k_exp<<<gx, 256>>>();
    k_out<<<go, b128>>>(out, 1);      // -> g_f

    // ---- layer 1 ----
    k_gemm_h<<<gh, b128>>>(nullptr, 1, w1, b1, MEMD);
    k_s<<<gs, b128>>>(a1w, a1b);
    k_e<<<ge, b256>>>(adj, a2w, a2b);
    k_exp<<<gx, 256>>>();
    k_out<<<go, b128>>>(out, 0);      // -> d_out
}